// round 15
// baseline (speedup 1.0000x reference)
#include <cuda_runtime.h>
#include <math.h>

#define FULL 0xffffffffu

// Problem constants
constexpr int B_ = 4;
constexpr int P_ = 2048;
constexpr int NPOS = B_ * P_;           // 8192
constexpr int NCHUNK = 64;              // 32-position chunks per sequence

// Scratch (device globals; no allocation in kernel_launch)
__device__ float g_enc_psi[NPOS * 32];
__device__ float g_enc[NPOS * 32];
__device__ float g_u[NPOS * 4];
__device__ float g_ct2[B_ * NCHUNK * 32];       // chunk totals of enc_psi
__device__ float g_ct4n[16 * NCHUNK * 32];      // chunk totals of u*enc per (b,h)
__device__ float g_ct4d[16 * NCHUNK];           // chunk totals of u per (b,h)

// combined[lane] for one position
__device__ __forceinline__ float combined_lane(float t, float v, int m, int lane) {
    if (lane < 8) {
        float sc;
        switch (lane >> 1) {
            case 0:  sc = 1.0f;   break;
            case 1:  sc = 0.1f;   break;
            case 2:  sc = 0.01f;  break;
            default: sc = 0.001f; break;
        }
        float r = t * sc;
        return (lane & 1) ? cosf(r) : sinf(r);
    } else if (lane == 8) {
        return v;
    } else if (lane < 31) {
        return (m == lane - 8) ? 1.0f : 0.0f;
    }
    return 0.0f;
}

// ---------------------------------------------------------------------------
// K1 v4: features + psi MLP + phi MLP + enc_psi chunk totals.
// Grid 256 (block = one 32-position chunk) x 512 threads (16 warps);
// warp = 2 positions -> 4096 warps total (~6.9 warps/SMSP for latency hiding).
// ---------------------------------------------------------------------------
__global__ __launch_bounds__(512) void k1_feat_mlps(
    const float* __restrict__ times, const float* __restrict__ values,
    const int* __restrict__ meas, const float* __restrict__ mask,
    const float* __restrict__ pw1, const float* __restrict__ pb1,
    const float* __restrict__ pw2, const float* __restrict__ pb2,
    const float* __restrict__ fw1, const float* __restrict__ fb1,
    const float* __restrict__ fw2, const float* __restrict__ fb2)
{
    __shared__ float4 s_pw1[8 * 32], s_pw2[8 * 32];
    __shared__ float4 s_fw1[8 * 32], s_fw2[8 * 32];
    __shared__ float  s_pb1[32], s_pb2[32], s_fb1[32], s_fb2[32];
    __shared__ float4 s_x4[16][2][8];
    __shared__ float4 s_h4[16][2][8];
    __shared__ float  s_part[16][32];    // per-warp enc_psi partial sums

    int tid = threadIdx.x;
    for (int i = tid; i < 8 * 32; i += 512) {
        int i4 = i >> 5, l = i & 31, r0 = i4 * 4;
        float p3 = (r0 + 3 < 31) ? pw1[(r0 + 3) * 32 + l] : 0.0f;
        float f3 = (r0 + 3 < 31) ? fw1[(r0 + 3) * 32 + l] : 0.0f;
        s_pw1[i] = make_float4(pw1[r0 * 32 + l], pw1[(r0 + 1) * 32 + l],
                               pw1[(r0 + 2) * 32 + l], p3);
        s_fw1[i] = make_float4(fw1[r0 * 32 + l], fw1[(r0 + 1) * 32 + l],
                               fw1[(r0 + 2) * 32 + l], f3);
        s_pw2[i] = make_float4(pw2[r0 * 32 + l], pw2[(r0 + 1) * 32 + l],
                               pw2[(r0 + 2) * 32 + l], pw2[(r0 + 3) * 32 + l]);
        s_fw2[i] = make_float4(fw2[r0 * 32 + l], fw2[(r0 + 1) * 32 + l],
                               fw2[(r0 + 2) * 32 + l], fw2[(r0 + 3) * 32 + l]);
    }
    if (tid < 32) { s_pb1[tid] = pb1[tid]; s_pb2[tid] = pb2[tid];
                    s_fb1[tid] = fb1[tid]; s_fb2[tid] = fb2[tid]; }
    __syncthreads();

    int lane = tid & 31;
    int w    = tid >> 5;                 // 0..15
    int pos0 = blockIdx.x * 32 + w * 2;
    int b    = blockIdx.x >> 6;
    int chunk = blockIdx.x & 63;

    float mk[2];
    #pragma unroll
    for (int q = 0; q < 2; q++) {
        int pos = pos0 + q;
        float t = times[pos], v = values[pos];
        mk[q] = mask[pos];
        int m = meas[pos];
        ((float*)&s_x4[w][q])[lane] = combined_lane(t, v, m, lane) * mk[q];
    }
    __syncwarp();

    float acc[2];

    // psi layer 1
    #pragma unroll
    for (int q = 0; q < 2; q++) acc[q] = s_pb1[lane];
    #pragma unroll
    for (int i4 = 0; i4 < 8; i4++) {
        float4 wv = s_pw1[i4 * 32 + lane];
        #pragma unroll
        for (int q = 0; q < 2; q++) {
            float4 xv = s_x4[w][q][i4];
            acc[q] += xv.x * wv.x; acc[q] += xv.y * wv.y;
            acc[q] += xv.z * wv.z; acc[q] += xv.w * wv.w;
        }
    }
    #pragma unroll
    for (int q = 0; q < 2; q++)
        ((float*)&s_h4[w][q])[lane] = fmaxf(acc[q], 0.0f) * mk[q];
    __syncwarp();

    // psi layer 2 (+ chunk partial)
    #pragma unroll
    for (int q = 0; q < 2; q++) acc[q] = s_pb2[lane];
    #pragma unroll
    for (int i4 = 0; i4 < 8; i4++) {
        float4 wv = s_pw2[i4 * 32 + lane];
        #pragma unroll
        for (int q = 0; q < 2; q++) {
            float4 xv = s_h4[w][q][i4];
            acc[q] += xv.x * wv.x; acc[q] += xv.y * wv.y;
            acc[q] += xv.z * wv.z; acc[q] += xv.w * wv.w;
        }
    }
    float psum = 0.0f;
    #pragma unroll
    for (int q = 0; q < 2; q++) {
        float ev = fmaxf(acc[q], 0.0f) * mk[q];
        g_enc_psi[(pos0 + q) * 32 + lane] = ev;
        psum += ev;
    }
    s_part[w][lane] = psum;
    __syncwarp();

    // phi layer 1
    #pragma unroll
    for (int q = 0; q < 2; q++) acc[q] = s_fb1[lane];
    #pragma unroll
    for (int i4 = 0; i4 < 8; i4++) {
        float4 wv = s_fw1[i4 * 32 + lane];
        #pragma unroll
        for (int q = 0; q < 2; q++) {
            float4 xv = s_x4[w][q][i4];
            acc[q] += xv.x * wv.x; acc[q] += xv.y * wv.y;
            acc[q] += xv.z * wv.z; acc[q] += xv.w * wv.w;
        }
    }
    #pragma unroll
    for (int q = 0; q < 2; q++)
        ((float*)&s_h4[w][q])[lane] = fmaxf(acc[q], 0.0f) * mk[q];
    __syncwarp();

    // phi layer 2
    #pragma unroll
    for (int q = 0; q < 2; q++) acc[q] = s_fb2[lane];
    #pragma unroll
    for (int i4 = 0; i4 < 8; i4++) {
        float4 wv = s_fw2[i4 * 32 + lane];
        #pragma unroll
        for (int q = 0; q < 2; q++) {
            float4 xv = s_h4[w][q][i4];
            acc[q] += xv.x * wv.x; acc[q] += xv.y * wv.y;
            acc[q] += xv.z * wv.z; acc[q] += xv.w * wv.w;
        }
    }
    #pragma unroll
    for (int q = 0; q < 2; q++)
        g_enc[(pos0 + q) * 32 + lane] = fmaxf(acc[q], 0.0f) * mk[q];

    // chunk total of enc_psi
    __syncthreads();
    if (w == 0) {
        float t = 0.0f;
        #pragma unroll
        for (int w2 = 0; w2 < 16; w2++) t += s_part[w2][lane];
        g_ct2[(b * NCHUNK + chunk) * 32 + lane] = t;
    }
}

// ---------------------------------------------------------------------------
// K3 v4: inline aggraw + agg matvec + keys matvec + preattn + u + k45 chunk
// totals. Grid 256 (block = chunk) x 512 threads (16 warps); Q=2.
// ---------------------------------------------------------------------------
__global__ __launch_bounds__(512) void k3_preattn(
    const float* __restrict__ times, const float* __restrict__ values,
    const int* __restrict__ meas, const float* __restrict__ mask,
    const float* __restrict__ arw, const float* __restrict__ arb,
    const float* __restrict__ wk, const float* __restrict__ wq)
{
    __shared__ float4 s_ar4[8 * 32];
    __shared__ float4 s_wk4[32 * 32];
    __shared__ float  s_ab[32], s_wq[64];
    __shared__ float4 s_g4[16][2][8];
    __shared__ float2 s_y2[16][2][32];
    __shared__ float  s_wp[16][32];
    __shared__ float  s_pn[16][4][32];
    __shared__ float  s_pd[16][4];

    int tid = threadIdx.x;
    for (int i = tid; i < 8 * 32; i += 512) {
        int i4 = i >> 5, l = i & 31, r0 = i4 * 4;
        s_ar4[i] = make_float4(arw[r0 * 32 + l], arw[(r0 + 1) * 32 + l],
                               arw[(r0 + 2) * 32 + l], arw[(r0 + 3) * 32 + l]);
    }
    for (int i = tid; i < 32 * 32; i += 512) {
        int i2 = i >> 5, l = i & 31, r0 = i2 * 2;
        float w2a = (r0 + 1 < 63) ? wk[(r0 + 1) * 64 + l]      : 0.0f;
        float w2b = (r0 + 1 < 63) ? wk[(r0 + 1) * 64 + l + 32] : 0.0f;
        s_wk4[i] = make_float4(wk[r0 * 64 + l], wk[r0 * 64 + l + 32], w2a, w2b);
    }
    if (tid < 32) s_ab[tid] = arb[tid];
    if (tid < 64) s_wq[tid] = wq[tid];

    int lane  = tid & 31;
    int w     = tid >> 5;                // 0..15
    int b     = blockIdx.x >> 6;
    int chunk = blockIdx.x & 63;
    int pos0  = blockIdx.x * 32 + w * 2;        // global position
    int lp0   = chunk * 32 + w * 2;             // LOCAL (within-sequence) position

    // Stage raw combined; load own-chunk enc_psi; within-warp prefix.
    float mk[2], cq[2];
    {
        float eq[2];
        #pragma unroll
        for (int q = 0; q < 2; q++) {
            int pos = pos0 + q;
            float t = times[pos], v = values[pos];
            mk[q] = mask[pos];
            int m = meas[pos];
            ((float*)s_y2[w][q])[lane] = combined_lane(t, v, m, lane);
            eq[q] = g_enc_psi[pos * 32 + lane];
        }
        cq[0] = eq[0];
        cq[1] = cq[0] + eq[1];
        s_wp[w][lane] = cq[1];
    }
    __syncthreads();   // covers weights, s_y2 low, s_wp

    // exclusive offset: preceding chunks (g_ct2) + preceding warps
    float off;
    {
        const float* ct = g_ct2 + (b * NCHUNK) * 32 + lane;
        float o0 = 0.f, o1 = 0.f, o2 = 0.f, o3 = 0.f;
        int k = 0;
        for (; k + 4 <= chunk; k += 4) {
            o0 += ct[k * 32];       o1 += ct[(k + 1) * 32];
            o2 += ct[(k + 2) * 32]; o3 += ct[(k + 3) * 32];
        }
        for (; k < chunk; k++) o0 += ct[k * 32];
        off = (o0 + o1) + (o2 + o3);
    }
    for (int w2 = 0; w2 < w; w2++) off += s_wp[w2][lane];

    // aggraw = cumsum / (LOCAL count) * mask -> staged for broadcast matvec
    #pragma unroll
    for (int q = 0; q < 2; q++) {
        float cum = off + cq[q];
        float agr = __fdividef(cum, (float)(lp0 + q + 1)) * mk[q];
        ((float*)&s_g4[w][q])[lane] = agr;
    }
    __syncwarp();

    // agg matvec (32x32)
    float agg[2];
    #pragma unroll
    for (int q = 0; q < 2; q++) agg[q] = s_ab[lane];
    #pragma unroll
    for (int i4 = 0; i4 < 8; i4++) {
        float4 wv = s_ar4[i4 * 32 + lane];
        #pragma unroll
        for (int q = 0; q < 2; q++) {
            float4 xv = s_g4[w][q][i4];
            agg[q] += xv.x * wv.x; agg[q] += xv.y * wv.y;
            agg[q] += xv.z * wv.z; agg[q] += xv.w * wv.w;
        }
    }
    #pragma unroll
    for (int q = 0; q < 2; q++) {
        ((float*)s_y2[w][q])[31 + lane] = agg[q] * mk[q];
        if (lane == 0) ((float*)s_y2[w][q])[63] = 0.0f;
    }
    __syncwarp();

    // keys matvec (63x64)
    float a0[2] = {0.f, 0.f}, a1[2] = {0.f, 0.f};
    #pragma unroll
    for (int i2 = 0; i2 < 32; i2++) {
        float4 wv = s_wk4[i2 * 32 + lane];
        #pragma unroll
        for (int q = 0; q < 2; q++) {
            float2 yv = s_y2[w][q][i2];
            a0[q] += yv.x * wv.x; a1[q] += yv.x * wv.y;
            a0[q] += yv.y * wv.z; a1[q] += yv.y * wv.w;
        }
    }

    int hh = lane & 3, dd = lane >> 2;
    float q0 = s_wq[hh * 16 + dd], q1 = s_wq[hh * 16 + dd + 8];
    float ufull[2];
    #pragma unroll
    for (int q = 0; q < 2; q++) {
        float part = a0[q] * mk[q] * q0 + a1[q] * mk[q] * q1;
        part += __shfl_xor_sync(FULL, part, 4);
        part += __shfl_xor_sync(FULL, part, 8);
        part += __shfl_xor_sync(FULL, part, 16);
        float pre = part * 0.25f * mk[q];
        ufull[q] = expf(pre);                    // lane l holds head l&3
        if (lane < 4) g_u[(pos0 + q) * 4 + lane] = ufull[q];
    }

    // k45 chunk totals: pn[h][lane] = sum_q u[q][h]*enc[q][lane]; pd[h] = sum_q u[q][h]
    {
        float e2q[2];
        #pragma unroll
        for (int q = 0; q < 2; q++) e2q[q] = g_enc[(pos0 + q) * 32 + lane];
        #pragma unroll
        for (int h = 0; h < 4; h++) {
            float s = 0.0f;
            #pragma unroll
            for (int q = 0; q < 2; q++)
                s += __shfl_sync(FULL, ufull[q], h) * e2q[q];
            s_pn[w][h][lane] = s;
        }
        if (lane < 4)
            s_pd[w][lane] = ufull[0] + ufull[1];
    }
    __syncthreads();

    if (w < 4) {
        int h = w;
        float t = 0.0f;
        #pragma unroll
        for (int w2 = 0; w2 < 16; w2++) t += s_pn[w2][h][lane];
        g_ct4n[((b * 4 + h) * NCHUNK + chunk) * 32 + lane] = t;
        if (lane == 0) {
            float td = 0.0f;
            #pragma unroll
            for (int w2 = 0; w2 < 16; w2++) td += s_pd[w2][h];
            g_ct4d[(b * 4 + h) * NCHUNK + chunk] = td;
        }
    }
}

// ---------------------------------------------------------------------------
// K45: fused scan + rho MLP (unchanged from R13).
// ---------------------------------------------------------------------------
__global__ __launch_bounds__(512, 2) void k45_fused(
    const float* __restrict__ mask,
    const float* __restrict__ rw1, const float* __restrict__ rb1,
    const float* __restrict__ rw2, const float* __restrict__ rb2,
    float* __restrict__ out)
{
    extern __shared__ char sm[];
    float4* s_w1 = (float4*)sm;                  // 2048 float4 = 32KB
    float4* s_w2 = (float4*)(sm + 32768);        // 1024 float4 = 16KB
    float*  s_a  = (float*) (sm + 49152);        // 32*128 fl   = 16KB
    float*  s_h  = (float*) (sm + 65536);        // 32*64 fl    =  8KB

    int tid  = threadIdx.x;
    int w    = tid >> 5, lane = tid & 31;
    int b    = blockIdx.x >> 6;
    int chunk = blockIdx.x & 63;
    int p0   = chunk * 32;                       // local position base

    if (w >= 4) {
        // ---- Phase 0b: stage weights (threads 128..511) ----
        int t = tid - 128;
        for (int i = t; i < 2048; i += 384) {
            int kp = i >> 5, l = i & 31, k = kp * 2;
            s_w1[i] = make_float4(rw1[k * 64 + l],       rw1[k * 64 + l + 32],
                                  rw1[(k + 1) * 64 + l], rw1[(k + 1) * 64 + l + 32]);
        }
        for (int i = t; i < 1024; i += 384) {
            int kp = i >> 5, l = i & 31, k = kp * 2;
            s_w2[i] = make_float4(rw2[k * 64 + l],       rw2[k * 64 + l + 32],
                                  rw2[(k + 1) * 64 + l], rw2[(k + 1) * 64 + l + 32]);
        }
    } else {
        // ---- Phase 0a: per-head causal scan (warp w = head h) ----
        int h  = w;
        int bh = b * 4 + h;

        // num offset from chunk totals (coalesced)
        float accn;
        {
            const float* ct = g_ct4n + (bh * NCHUNK) * 32 + lane;
            float o0 = 0.f, o1 = 0.f, o2 = 0.f, o3 = 0.f;
            int k = 0;
            for (; k + 4 <= chunk; k += 4) {
                o0 += ct[k * 32];       o1 += ct[(k + 1) * 32];
                o2 += ct[(k + 2) * 32]; o3 += ct[(k + 3) * 32];
            }
            for (; k < chunk; k++) o0 += ct[k * 32];
            accn = (o0 + o1) + (o2 + o3);
        }
        // den offset
        float accu;
        {
            const float* cd = g_ct4d + bh * NCHUNK;
            float myd = 0.0f;
            if (lane < chunk)      myd  = cd[lane];
            if (lane + 32 < chunk) myd += cd[lane + 32];
            #pragma unroll
            for (int o = 16; o >= 1; o >>= 1) myd += __shfl_xor_sync(FULL, myd, o);
            accu = myd;
        }

        const float* up = g_u   + b * P_ * 4 + h;
        const float* ep = g_enc + b * P_ * 32 + lane;
        const float* mp = mask  + b * P_;

        // 4 tiles of 8 positions (keeps regs under 63 for 2-block residency)
        #pragma unroll
        for (int tile = 0; tile < 4; tile++) {
            int base = p0 + tile * 8;
            float uu[8], ee[8], mm[8];
            #pragma unroll
            for (int j = 0; j < 8; j++) {
                uu[j] = up[(base + j) * 4];
                ee[j] = ep[(base + j) * 32];
                mm[j] = mp[base + j];
            }
            #pragma unroll
            for (int j = 0; j < 8; j++) {
                accn += uu[j] * ee[j];
                accu += uu[j];
                float sc = __fdividef(mm[j] * mm[j], accu);
                s_a[(tile * 8 + j) * 128 + h * 32 + lane] = accn * sc;
            }
        }
    }
    __syncthreads();

    // ---- Phase 1: rho MLP, Q=2 positions per warp ----
    int pl0 = w * 2;                      // local positions pl0, pl0+1
    int gp0 = b * P_ + p0 + pl0;
    float mks[2] = { mask[gp0], mask[gp0 + 1] };
    const float4* s_a4 = (const float4*)s_a;

    float acc0[2], acc1[2];
    {
        float b0 = rb1[lane], b1v = rb1[lane + 32];
        acc0[0] = b0;  acc0[1] = b0;
        acc1[0] = b1v; acc1[1] = b1v;
    }

    #pragma unroll 4
    for (int g = 0; g < 32; g++) {                   // 4 k's per group
        float4 wa = s_w1[(2 * g) * 32 + lane];       // k=4g, 4g+1
        float4 wb = s_w1[(2 * g + 1) * 32 + lane];   // k=4g+2, 4g+3
        #pragma unroll
        for (int q = 0; q < 2; q++) {
            float4 av = s_a4[(pl0 + q) * 32 + g];    // broadcast
            acc0[q] += av.x * wa.x; acc1[q] += av.x * wa.y;
            acc0[q] += av.y * wa.z; acc1[q] += av.y * wa.w;
            acc0[q] += av.z * wb.x; acc1[q] += av.z * wb.y;
            acc0[q] += av.w * wb.z; acc1[q] += av.w * wb.w;
        }
    }

    // relu + mask -> s_h
    #pragma unroll
    for (int q = 0; q < 2; q++) {
        float* hp = s_h + (pl0 + q) * 64;
        hp[lane]      = fmaxf(acc0[q], 0.0f) * mks[q];
        hp[lane + 32] = fmaxf(acc1[q], 0.0f) * mks[q];
    }
    __syncwarp();

    // ---- layer 2 ----
    {
        float b0 = rb2[lane], b1v = rb2[lane + 32];
        acc0[0] = b0;  acc0[1] = b0;
        acc1[0] = b1v; acc1[1] = b1v;
    }

    #pragma unroll 4
    for (int g = 0; g < 16; g++) {
        float4 wa = s_w2[(2 * g) * 32 + lane];
        float4 wb = s_w2[(2 * g + 1) * 32 + lane];
        #pragma unroll
        for (int q = 0; q < 2; q++) {
            float4 av = *(const float4*)(s_h + (pl0 + q) * 64 + 4 * g);  // bcast
            acc0[q] += av.x * wa.x; acc1[q] += av.x * wa.y;
            acc0[q] += av.y * wa.z; acc1[q] += av.y * wa.w;
            acc0[q] += av.z * wb.x; acc1[q] += av.z * wb.y;
            acc0[q] += av.w * wb.z; acc1[q] += av.w * wb.w;
        }
    }

    // relu + mask -> output
    #pragma unroll
    for (int q = 0; q < 2; q++) {
        int gpos = gp0 + q;
        out[gpos * 64 + lane]      = fmaxf(acc0[q], 0.0f) * mks[q];
        out[gpos * 64 + lane + 32] = fmaxf(acc1[q], 0.0f) * mks[q];
    }
}

// ---------------------------------------------------------------------------
extern "C" void kernel_launch(void* const* d_in, const int* in_sizes, int n_in,
                              void* d_out, int out_size)
{
    const float* times   = (const float*)d_in[0];
    const float* values  = (const float*)d_in[1];
    const int*   meas    = (const int*)  d_in[2];
    const float* mask    = (const float*)d_in[3];
    const float* psi_w1  = (const float*)d_in[4];
    const float* psi_b1  = (const float*)d_in[5];
    const float* psi_w2  = (const float*)d_in[6];
    const float* psi_b2  = (const float*)d_in[7];
    const float* arho_w  = (const float*)d_in[8];
    const float* arho_b  = (const float*)d_in[9];
    const float* W_k     = (const float*)d_in[10];
    const float* W_q     = (const float*)d_in[11];
    const float* phi_w1  = (const float*)d_in[12];
    const float* phi_b1  = (const float*)d_in[13];
    const float* phi_w2  = (const float*)d_in[14];
    const float* phi_b2  = (const float*)d_in[15];
    const float* rho_w1  = (const float*)d_in[16];
    const float* rho_b1  = (const float*)d_in[17];
    const float* rho_w2  = (const float*)d_in[18];
    const float* rho_b2  = (const float*)d_in[19];
    float* out = (float*)d_out;

    cudaFuncSetAttribute(k45_fused, cudaFuncAttributeMaxDynamicSharedMemorySize, 73728);

    k1_feat_mlps<<<256, 512>>>(times, values, meas, mask,
                               psi_w1, psi_b1, psi_w2, psi_b2,
                               phi_w1, phi_b1, phi_w2, phi_b2);
    k3_preattn<<<256, 512>>>(times, values, meas, mask,
                             arho_w, arho_b, W_k, W_q);
    k45_fused<<<256, 512, 73728>>>(mask, rho_w1, rho_b1, rho_w2, rho_b2, out);
}

// round 16
// speedup vs baseline: 1.0608x; 1.0608x over previous
#include <cuda_runtime.h>
#include <math.h>

#define FULL 0xffffffffu

// Problem constants
constexpr int B_ = 4;
constexpr int P_ = 2048;
constexpr int NPOS = B_ * P_;           // 8192
constexpr int NCHUNK = 64;              // 32-position chunks per sequence

// Scratch (device globals; no allocation in kernel_launch)
__device__ float g_enc_psi[NPOS * 32];
__device__ float g_enc[NPOS * 32];
__device__ float g_u[NPOS * 4];
__device__ float g_ct2[B_ * NCHUNK * 32];       // chunk totals of enc_psi
__device__ float g_ct4n[16 * NCHUNK * 32];      // chunk totals of u*enc per (b,h)
__device__ float g_ct4d[16 * NCHUNK];           // chunk totals of u per (b,h)

// combined[lane] for one position
__device__ __forceinline__ float combined_lane(float t, float v, int m, int lane) {
    if (lane < 8) {
        float sc;
        switch (lane >> 1) {
            case 0:  sc = 1.0f;   break;
            case 1:  sc = 0.1f;   break;
            case 2:  sc = 0.01f;  break;
            default: sc = 0.001f; break;
        }
        float r = t * sc;
        return (lane & 1) ? cosf(r) : sinf(r);
    } else if (lane == 8) {
        return v;
    } else if (lane < 31) {
        return (m == lane - 8) ? 1.0f : 0.0f;
    }
    return 0.0f;
}

// ---------------------------------------------------------------------------
// K1: features + psi MLP + phi MLP + enc_psi chunk totals.
// Grid 256 (block = one 32-position chunk) x 256 threads; warp = 4 positions.
// (R13 configuration — the best measured k1.)
// ---------------------------------------------------------------------------
__global__ __launch_bounds__(256) void k1_feat_mlps(
    const float* __restrict__ times, const float* __restrict__ values,
    const int* __restrict__ meas, const float* __restrict__ mask,
    const float* __restrict__ pw1, const float* __restrict__ pb1,
    const float* __restrict__ pw2, const float* __restrict__ pb2,
    const float* __restrict__ fw1, const float* __restrict__ fb1,
    const float* __restrict__ fw2, const float* __restrict__ fb2)
{
    __shared__ float4 s_pw1[8 * 32], s_pw2[8 * 32];
    __shared__ float4 s_fw1[8 * 32], s_fw2[8 * 32];
    __shared__ float  s_pb1[32], s_pb2[32], s_fb1[32], s_fb2[32];
    __shared__ float4 s_x4[8][4][8];
    __shared__ float4 s_h4[8][4][8];
    __shared__ float  s_part[8][32];     // per-warp enc_psi partial sums

    int tid = threadIdx.x;
    for (int i = tid; i < 8 * 32; i += 256) {
        int i4 = i >> 5, l = i & 31, r0 = i4 * 4;
        float p3 = (r0 + 3 < 31) ? pw1[(r0 + 3) * 32 + l] : 0.0f;
        float f3 = (r0 + 3 < 31) ? fw1[(r0 + 3) * 32 + l] : 0.0f;
        s_pw1[i] = make_float4(pw1[r0 * 32 + l], pw1[(r0 + 1) * 32 + l],
                               pw1[(r0 + 2) * 32 + l], p3);
        s_fw1[i] = make_float4(fw1[r0 * 32 + l], fw1[(r0 + 1) * 32 + l],
                               fw1[(r0 + 2) * 32 + l], f3);
        s_pw2[i] = make_float4(pw2[r0 * 32 + l], pw2[(r0 + 1) * 32 + l],
                               pw2[(r0 + 2) * 32 + l], pw2[(r0 + 3) * 32 + l]);
        s_fw2[i] = make_float4(fw2[r0 * 32 + l], fw2[(r0 + 1) * 32 + l],
                               fw2[(r0 + 2) * 32 + l], fw2[(r0 + 3) * 32 + l]);
    }
    if (tid < 32) { s_pb1[tid] = pb1[tid]; s_pb2[tid] = pb2[tid];
                    s_fb1[tid] = fb1[tid]; s_fb2[tid] = fb2[tid]; }
    __syncthreads();

    int lane = tid & 31;
    int w    = tid >> 5;
    int pos0 = blockIdx.x * 32 + w * 4;
    int b    = blockIdx.x >> 6;
    int chunk = blockIdx.x & 63;

    float mk[4];
    #pragma unroll
    for (int q = 0; q < 4; q++) {
        int pos = pos0 + q;
        float t = times[pos], v = values[pos];
        mk[q] = mask[pos];
        int m = meas[pos];
        ((float*)&s_x4[w][q])[lane] = combined_lane(t, v, m, lane) * mk[q];
    }
    __syncwarp();

    float acc[4];

    // psi layer 1
    #pragma unroll
    for (int q = 0; q < 4; q++) acc[q] = s_pb1[lane];
    #pragma unroll
    for (int i4 = 0; i4 < 8; i4++) {
        float4 wv = s_pw1[i4 * 32 + lane];
        #pragma unroll
        for (int q = 0; q < 4; q++) {
            float4 xv = s_x4[w][q][i4];
            acc[q] += xv.x * wv.x; acc[q] += xv.y * wv.y;
            acc[q] += xv.z * wv.z; acc[q] += xv.w * wv.w;
        }
    }
    #pragma unroll
    for (int q = 0; q < 4; q++)
        ((float*)&s_h4[w][q])[lane] = fmaxf(acc[q], 0.0f) * mk[q];
    __syncwarp();

    // psi layer 2 (+ chunk partial)
    #pragma unroll
    for (int q = 0; q < 4; q++) acc[q] = s_pb2[lane];
    #pragma unroll
    for (int i4 = 0; i4 < 8; i4++) {
        float4 wv = s_pw2[i4 * 32 + lane];
        #pragma unroll
        for (int q = 0; q < 4; q++) {
            float4 xv = s_h4[w][q][i4];
            acc[q] += xv.x * wv.x; acc[q] += xv.y * wv.y;
            acc[q] += xv.z * wv.z; acc[q] += xv.w * wv.w;
        }
    }
    float psum = 0.0f;
    #pragma unroll
    for (int q = 0; q < 4; q++) {
        float ev = fmaxf(acc[q], 0.0f) * mk[q];
        g_enc_psi[(pos0 + q) * 32 + lane] = ev;
        psum += ev;
    }
    s_part[w][lane] = psum;
    __syncwarp();

    // phi layer 1
    #pragma unroll
    for (int q = 0; q < 4; q++) acc[q] = s_fb1[lane];
    #pragma unroll
    for (int i4 = 0; i4 < 8; i4++) {
        float4 wv = s_fw1[i4 * 32 + lane];
        #pragma unroll
        for (int q = 0; q < 4; q++) {
            float4 xv = s_x4[w][q][i4];
            acc[q] += xv.x * wv.x; acc[q] += xv.y * wv.y;
            acc[q] += xv.z * wv.z; acc[q] += xv.w * wv.w;
        }
    }
    #pragma unroll
    for (int q = 0; q < 4; q++)
        ((float*)&s_h4[w][q])[lane] = fmaxf(acc[q], 0.0f) * mk[q];
    __syncwarp();

    // phi layer 2
    #pragma unroll
    for (int q = 0; q < 4; q++) acc[q] = s_fb2[lane];
    #pragma unroll
    for (int i4 = 0; i4 < 8; i4++) {
        float4 wv = s_fw2[i4 * 32 + lane];
        #pragma unroll
        for (int q = 0; q < 4; q++) {
            float4 xv = s_h4[w][q][i4];
            acc[q] += xv.x * wv.x; acc[q] += xv.y * wv.y;
            acc[q] += xv.z * wv.z; acc[q] += xv.w * wv.w;
        }
    }
    #pragma unroll
    for (int q = 0; q < 4; q++)
        g_enc[(pos0 + q) * 32 + lane] = fmaxf(acc[q], 0.0f) * mk[q];

    // chunk total of enc_psi
    __syncthreads();
    if (w == 0) {
        float t = 0.0f;
        #pragma unroll
        for (int w2 = 0; w2 < 8; w2++) t += s_part[w2][lane];
        g_ct2[(b * NCHUNK + chunk) * 32 + lane] = t;
    }
}

// ---------------------------------------------------------------------------
// K3 v5: ALGEBRAIC COLLAPSE — keys are never materialized.
//   preattn[h] = comb2 · wq_eff[:,h],  wq_eff[j,h] = sum_d W_k[j,4d+h]W_q[h,d]/4
// wq_eff is 63x4 (1KB smem, computed once per block). The 63x64 keys matvec
// per position becomes 8 FFMA + a 4-value warp butterfly.
// Grid 256 (block = chunk) x 256 threads; warp = 4 positions.
// ---------------------------------------------------------------------------
__global__ __launch_bounds__(256) void k3_preattn(
    const float* __restrict__ times, const float* __restrict__ values,
    const int* __restrict__ meas, const float* __restrict__ mask,
    const float* __restrict__ arw, const float* __restrict__ arb,
    const float* __restrict__ wk, const float* __restrict__ wq)
{
    __shared__ float4 s_ar4[8 * 32];      // arho rows packed x4 (4KB)
    __shared__ float  s_ab[32];
    __shared__ float4 s_we4[64];          // wq_eff rows (63 + pad), x0.25 folded
    __shared__ float4 s_g4[8][4][8];      // staged aggraw for broadcast matvec
    __shared__ float  s_wp[8][32];
    __shared__ float  s_pn[8][4][32];
    __shared__ float  s_pd[8][4];

    int tid = threadIdx.x;
    for (int i = tid; i < 8 * 32; i += 256) {
        int i4 = i >> 5, l = i & 31, r0 = i4 * 4;
        s_ar4[i] = make_float4(arw[r0 * 32 + l], arw[(r0 + 1) * 32 + l],
                               arw[(r0 + 2) * 32 + l], arw[(r0 + 3) * 32 + l]);
    }
    if (tid < 32) s_ab[tid] = arb[tid];
    // wq_eff: entry (j,h) = sum_d wk[j*64 + 4d + h] * wq[h*16 + d], x 0.25
    {
        if (tid < 252) {
            int j = tid >> 2, h = tid & 3;
            float s = 0.0f;
            #pragma unroll
            for (int d = 0; d < 16; d++)
                s += wk[j * 64 + d * 4 + h] * wq[h * 16 + d];
            ((float*)s_we4)[tid] = s * 0.25f;
        } else {
            ((float*)s_we4)[tid] = 0.0f;    // pad rows (j=63)
        }
    }

    int lane  = tid & 31;
    int w     = tid >> 5;
    int b     = blockIdx.x >> 6;
    int chunk = blockIdx.x & 63;
    int pos0  = blockIdx.x * 32 + w * 4;        // global position
    int lp0   = chunk * 32 + w * 4;             // LOCAL (within-sequence) position

    // Raw combined in registers; own-chunk enc_psi; within-warp prefix.
    float mk[4], cq[4], xraw[4];
    {
        float eq[4];
        #pragma unroll
        for (int q = 0; q < 4; q++) {
            int pos = pos0 + q;
            float t = times[pos], v = values[pos];
            mk[q] = mask[pos];
            int m = meas[pos];
            xraw[q] = combined_lane(t, v, m, lane);   // RAW (lane 31 -> 0)
            eq[q] = g_enc_psi[pos * 32 + lane];
        }
        cq[0] = eq[0];
        cq[1] = cq[0] + eq[1];
        cq[2] = cq[1] + eq[2];
        cq[3] = cq[2] + eq[3];
        s_wp[w][lane] = cq[3];
    }
    __syncthreads();   // covers weights, s_we4, s_wp

    // exclusive offset: preceding chunks (g_ct2) + preceding warps
    float off;
    {
        const float* ct = g_ct2 + (b * NCHUNK) * 32 + lane;
        float o0 = 0.f, o1 = 0.f, o2 = 0.f, o3 = 0.f;
        int k = 0;
        for (; k + 4 <= chunk; k += 4) {
            o0 += ct[k * 32];       o1 += ct[(k + 1) * 32];
            o2 += ct[(k + 2) * 32]; o3 += ct[(k + 3) * 32];
        }
        for (; k < chunk; k++) o0 += ct[k * 32];
        off = (o0 + o1) + (o2 + o3);
    }
    #pragma unroll
    for (int w2 = 0; w2 < 8; w2++)
        if (w2 < w) off += s_wp[w2][lane];

    // aggraw = cumsum / (LOCAL count) * mask -> staged for broadcast matvec
    #pragma unroll
    for (int q = 0; q < 4; q++) {
        float cum = off + cq[q];
        float agr = __fdividef(cum, (float)(lp0 + q + 1)) * mk[q];
        ((float*)&s_g4[w][q])[lane] = agr;
    }
    __syncwarp();

    // agg matvec (32x32)
    float agg[4];
    #pragma unroll
    for (int q = 0; q < 4; q++) agg[q] = s_ab[lane];
    #pragma unroll
    for (int i4 = 0; i4 < 8; i4++) {
        float4 wv = s_ar4[i4 * 32 + lane];
        #pragma unroll
        for (int q = 0; q < 4; q++) {
            float4 xv = s_g4[w][q][i4];
            agg[q] += xv.x * wv.x; agg[q] += xv.y * wv.y;
            agg[q] += xv.z * wv.z; agg[q] += xv.w * wv.w;
        }
    }

    // preattn via wq_eff: lane contributes rows j=lane (comb) and j=31+lane (agg)
    float4 wec = s_we4[lane];         // comb rows (lane 31 -> xraw=0, harmless)
    float4 wea = s_we4[31 + lane];    // agg rows 31..62
    int hh = lane & 3;
    float ufull[4];
    #pragma unroll
    for (int q = 0; q < 4; q++) {
        float am = agg[q] * mk[q];
        float p0 = xraw[q] * wec.x + am * wea.x;
        float p1 = xraw[q] * wec.y + am * wea.y;
        float p2 = xraw[q] * wec.z + am * wea.z;
        float p3 = xraw[q] * wec.w + am * wea.w;
        #pragma unroll
        for (int o = 16; o >= 1; o >>= 1) {
            p0 += __shfl_xor_sync(FULL, p0, o);
            p1 += __shfl_xor_sync(FULL, p1, o);
            p2 += __shfl_xor_sync(FULL, p2, o);
            p3 += __shfl_xor_sync(FULL, p3, o);
        }
        float ph = (hh == 0) ? p0 : (hh == 1) ? p1 : (hh == 2) ? p2 : p3;
        float pre = ph * mk[q] * mk[q];
        ufull[q] = expf(pre);                    // lane l holds head l&3
        if (lane < 4) g_u[(pos0 + q) * 4 + lane] = ufull[q];
    }

    // k45 chunk totals: pn[h][lane] = sum_q u[q][h]*enc[q][lane]; pd[h] = sum_q u[q][h]
    {
        float e2q[4];
        #pragma unroll
        for (int q = 0; q < 4; q++) e2q[q] = g_enc[(pos0 + q) * 32 + lane];
        #pragma unroll
        for (int h = 0; h < 4; h++) {
            float s = 0.0f;
            #pragma unroll
            for (int q = 0; q < 4; q++)
                s += __shfl_sync(FULL, ufull[q], h) * e2q[q];
            s_pn[w][h][lane] = s;
        }
        if (lane < 4)
            s_pd[w][lane] = ufull[0] + ufull[1] + ufull[2] + ufull[3];
    }
    __syncthreads();

    if (w < 4) {
        int h = w;
        float t = 0.0f;
        #pragma unroll
        for (int w2 = 0; w2 < 8; w2++) t += s_pn[w2][h][lane];
        g_ct4n[((b * 4 + h) * NCHUNK + chunk) * 32 + lane] = t;
        if (lane == 0) {
            float td = 0.0f;
            #pragma unroll
            for (int w2 = 0; w2 < 8; w2++) td += s_pd[w2][h];
            g_ct4d[(b * 4 + h) * NCHUNK + chunk] = td;
        }
    }
}

// ---------------------------------------------------------------------------
// K45: fused scan + rho MLP (unchanged from R13).
// ---------------------------------------------------------------------------
__global__ __launch_bounds__(512, 2) void k45_fused(
    const float* __restrict__ mask,
    const float* __restrict__ rw1, const float* __restrict__ rb1,
    const float* __restrict__ rw2, const float* __restrict__ rb2,
    float* __restrict__ out)
{
    extern __shared__ char sm[];
    float4* s_w1 = (float4*)sm;                  // 2048 float4 = 32KB
    float4* s_w2 = (float4*)(sm + 32768);        // 1024 float4 = 16KB
    float*  s_a  = (float*) (sm + 49152);        // 32*128 fl   = 16KB
    float*  s_h  = (float*) (sm + 65536);        // 32*64 fl    =  8KB

    int tid  = threadIdx.x;
    int w    = tid >> 5, lane = tid & 31;
    int b    = blockIdx.x >> 6;
    int chunk = blockIdx.x & 63;
    int p0   = chunk * 32;                       // local position base

    if (w >= 4) {
        // ---- Phase 0b: stage weights (threads 128..511) ----
        int t = tid - 128;
        for (int i = t; i < 2048; i += 384) {
            int kp = i >> 5, l = i & 31, k = kp * 2;
            s_w1[i] = make_float4(rw1[k * 64 + l],       rw1[k * 64 + l + 32],
                                  rw1[(k + 1) * 64 + l], rw1[(k + 1) * 64 + l + 32]);
        }
        for (int i = t; i < 1024; i += 384) {
            int kp = i >> 5, l = i & 31, k = kp * 2;
            s_w2[i] = make_float4(rw2[k * 64 + l],       rw2[k * 64 + l + 32],
                                  rw2[(k + 1) * 64 + l], rw2[(k + 1) * 64 + l + 32]);
        }
    } else {
        // ---- Phase 0a: per-head causal scan (warp w = head h) ----
        int h  = w;
        int bh = b * 4 + h;

        float accn;
        {
            const float* ct = g_ct4n + (bh * NCHUNK) * 32 + lane;
            float o0 = 0.f, o1 = 0.f, o2 = 0.f, o3 = 0.f;
            int k = 0;
            for (; k + 4 <= chunk; k += 4) {
                o0 += ct[k * 32];       o1 += ct[(k + 1) * 32];
                o2 += ct[(k + 2) * 32]; o3 += ct[(k + 3) * 32];
            }
            for (; k < chunk; k++) o0 += ct[k * 32];
            accn = (o0 + o1) + (o2 + o3);
        }
        float accu;
        {
            const float* cd = g_ct4d + bh * NCHUNK;
            float myd = 0.0f;
            if (lane < chunk)      myd  = cd[lane];
            if (lane + 32 < chunk) myd += cd[lane + 32];
            #pragma unroll
            for (int o = 16; o >= 1; o >>= 1) myd += __shfl_xor_sync(FULL, myd, o);
            accu = myd;
        }

        const float* up = g_u   + b * P_ * 4 + h;
        const float* ep = g_enc + b * P_ * 32 + lane;
        const float* mp = mask  + b * P_;

        #pragma unroll
        for (int tile = 0; tile < 4; tile++) {
            int base = p0 + tile * 8;
            float uu[8], ee[8], mm[8];
            #pragma unroll
            for (int j = 0; j < 8; j++) {
                uu[j] = up[(base + j) * 4];
                ee[j] = ep[(base + j) * 32];
                mm[j] = mp[base + j];
            }
            #pragma unroll
            for (int j = 0; j < 8; j++) {
                accn += uu[j] * ee[j];
                accu += uu[j];
                float sc = __fdividef(mm[j] * mm[j], accu);
                s_a[(tile * 8 + j) * 128 + h * 32 + lane] = accn * sc;
            }
        }
    }
    __syncthreads();

    // ---- Phase 1: rho MLP, Q=2 positions per warp ----
    int pl0 = w * 2;
    int gp0 = b * P_ + p0 + pl0;
    float mks[2] = { mask[gp0], mask[gp0 + 1] };
    const float4* s_a4 = (const float4*)s_a;

    float acc0[2], acc1[2];
    {
        float b0 = rb1[lane], b1v = rb1[lane + 32];
        acc0[0] = b0;  acc0[1] = b0;
        acc1[0] = b1v; acc1[1] = b1v;
    }

    #pragma unroll 4
    for (int g = 0; g < 32; g++) {
        float4 wa = s_w1[(2 * g) * 32 + lane];
        float4 wb = s_w1[(2 * g + 1) * 32 + lane];
        #pragma unroll
        for (int q = 0; q < 2; q++) {
            float4 av = s_a4[(pl0 + q) * 32 + g];
            acc0[q] += av.x * wa.x; acc1[q] += av.x * wa.y;
            acc0[q] += av.y * wa.z; acc1[q] += av.y * wa.w;
            acc0[q] += av.z * wb.x; acc1[q] += av.z * wb.y;
            acc0[q] += av.w * wb.z; acc1[q] += av.w * wb.w;
        }
    }

    #pragma unroll
    for (int q = 0; q < 2; q++) {
        float* hp = s_h + (pl0 + q) * 64;
        hp[lane]      = fmaxf(acc0[q], 0.0f) * mks[q];
        hp[lane + 32] = fmaxf(acc1[q], 0.0f) * mks[q];
    }
    __syncwarp();

    {
        float b0 = rb2[lane], b1v = rb2[lane + 32];
        acc0[0] = b0;  acc0[1] = b0;
        acc1[0] = b1v; acc1[1] = b1v;
    }

    #pragma unroll 4
    for (int g = 0; g < 16; g++) {
        float4 wa = s_w2[(2 * g) * 32 + lane];
        float4 wb = s_w2[(2 * g + 1) * 32 + lane];
        #pragma unroll
        for (int q = 0; q < 2; q++) {
            float4 av = *(const float4*)(s_h + (pl0 + q) * 64 + 4 * g);
            acc0[q] += av.x * wa.x; acc1[q] += av.x * wa.y;
            acc0[q] += av.y * wa.z; acc1[q] += av.y * wa.w;
            acc0[q] += av.z * wb.x; acc1[q] += av.z * wb.y;
            acc0[q] += av.w * wb.z; acc1[q] += av.w * wb.w;
        }
    }

    #pragma unroll
    for (int q = 0; q < 2; q++) {
        int gpos = gp0 + q;
        out[gpos * 64 + lane]      = fmaxf(acc0[q], 0.0f) * mks[q];
        out[gpos * 64 + lane + 32] = fmaxf(acc1[q], 0.0f) * mks[q];
    }
}

// ---------------------------------------------------------------------------
extern "C" void kernel_launch(void* const* d_in, const int* in_sizes, int n_in,
                              void* d_out, int out_size)
{
    const float* times   = (const float*)d_in[0];
    const float* values  = (const float*)d_in[1];
    const int*   meas    = (const int*)  d_in[2];
    const float* mask    = (const float*)d_in[3];
    const float* psi_w1  = (const float*)d_in[4];
    const float* psi_b1  = (const float*)d_in[5];
    const float* psi_w2  = (const float*)d_in[6];
    const float* psi_b2  = (const float*)d_in[7];
    const float* arho_w  = (const float*)d_in[8];
    const float* arho_b  = (const float*)d_in[9];
    const float* W_k     = (const float*)d_in[10];
    const float* W_q     = (const float*)d_in[11];
    const float* phi_w1  = (const float*)d_in[12];
    const float* phi_b1  = (const float*)d_in[13];
    const float* phi_w2  = (const float*)d_in[14];
    const float* phi_b2  = (const float*)d_in[15];
    const float* rho_w1  = (const float*)d_in[16];
    const float* rho_b1  = (const float*)d_in[17];
    const float* rho_w2  = (const float*)d_in[18];
    const float* rho_b2  = (const float*)d_in[19];
    float* out = (float*)d_out;

    cudaFuncSetAttribute(k45_fused, cudaFuncAttributeMaxDynamicSharedMemorySize, 73728);

    k1_feat_mlps<<<256, 256>>>(times, values, meas, mask,
                               psi_w1, psi_b1, psi_w2, psi_b2,
                               phi_w1, phi_b1, phi_w2, phi_b2);
    k3_preattn<<<256, 256>>>(times, values, meas, mask,
                             arho_w, arho_b, W_k, W_q);
    k45_fused<<<256, 512, 73728>>>(mask, rho_w1, rho_b1, rho_w2, rho_b2, out);
}

// round 17
// speedup vs baseline: 1.1834x; 1.1156x over previous
#include <cuda_runtime.h>
#include <math.h>

#define FULL 0xffffffffu

// Problem constants
constexpr int B_ = 4;
constexpr int P_ = 2048;
constexpr int NCHUNK = 64;              // 32-position chunks per sequence
constexpr int GRID = 256;               // one block per (b, chunk)

// Cross-block scratch (tiny chunk-total arrays only)
__device__ float g_ct2[B_ * NCHUNK * 32];       // chunk totals of enc_psi
__device__ float g_ct4n[16 * NCHUNK * 32];      // chunk totals of u*enc per (b,h)
__device__ float g_ct4d[16 * NCHUNK];           // chunk totals of u per (b,h)
__device__ unsigned g_bcnt[2];                  // grid-barrier counters (monotonic)

// ---- software grid barrier (graph-replay safe: monotonic, no reset) --------
__device__ __forceinline__ void grid_barrier(int slot) {
    __syncthreads();
    if (threadIdx.x == 0) {
        __threadfence();
        unsigned old = atomicAdd(&g_bcnt[slot], 1u);
        unsigned target = (old & ~255u) + 256u;       // GRID = 256
        while ((int)(*(volatile unsigned*)&g_bcnt[slot] - target) < 0) { }
    }
    __syncthreads();
}

// combined[lane] for one position (fast sin/cos: |err| ~1e-6 abs at t<=100)
__device__ __forceinline__ float combined_lane(float t, float v, int m, int lane) {
    if (lane < 8) {
        float sc;
        switch (lane >> 1) {
            case 0:  sc = 1.0f;   break;
            case 1:  sc = 0.1f;   break;
            case 2:  sc = 0.01f;  break;
            default: sc = 0.001f; break;
        }
        float r = t * sc;
        return (lane & 1) ? __cosf(r) : __sinf(r);
    } else if (lane == 8) {
        return v;
    } else if (lane < 31) {
        return (m == lane - 8) ? 1.0f : 0.0f;
    }
    return 0.0f;
}

// ---- smem layout (bytes), one extern buffer, regions reused across phases --
#define OFF_WP1   0        // A: psi w1 (8*32 float4 = 4KB)
#define OFF_WP2   4096     // A: psi w2
#define OFF_WF1   8192     // A: phi w1
#define OFF_WF2   12288    // A: phi w2
#define OFF_CW1   0        // C: rho w1 k-pair (2048 float4 = 32KB) — after A dead
#define OFF_CW2   32768    // C: rho w2 (1024 float4 = 16KB)
#define OFF_SX4   32768    // A: staged masked inputs (4KB) — dead before CW2 staged
#define OFF_SH4   36864    // A: staged hidden (4KB)
#define OFF_AR4   49152    // B: arho w packed (4KB)
#define OFF_WE    53248    // B: wq_eff (256 floats = 1KB)
#define OFF_WPX   54272    // B: per-warp prefix (1KB)
#define OFF_PN    55296    // B: pn partials (8*4*32 = 4KB)
#define OFF_PD    59392    // B: pd partials (128B)
#define OFF_G4    59520    // B: staged aggraw (4KB) -> ends 63616
#define OFF_CA    49152    // C: s_a activations (32*128 = 16KB) — after B dead
#define OFF_CH    65536    // C: s_h hidden (8KB); A: s_part (1KB)
#define OFF_COMB  73728    // persistent: raw combined (32*32 = 4KB)
#define OFF_EPSI  77824    // persistent: enc_psi own chunk (4KB)
#define OFF_ENC   81920    // persistent: enc own chunk (4KB)
#define OFF_U     86016    // persistent: u own chunk (32*4 = 512B)
#define OFF_MASK  86528    // persistent: mask (128B)
#define OFF_BIAS  86656    // A biases (4*128B) + B arb (128B) = 640B
#define SMEM_TOTAL 87296

// ---------------------------------------------------------------------------
// MEGA-KERNEL: block = one 32-position chunk; 256 threads (8 warps).
// Phase A: features + psi/phi MLPs (smem-resident) + ct2 -> barrier 0
// Phase B: aggraw + agg matvec + collapsed preattn + u + ct4 -> barrier 1
// Phase C: per-head scans (smem) + rho MLP -> out
// ---------------------------------------------------------------------------
__global__ __launch_bounds__(256, 2) void mega(
    const float* __restrict__ times, const float* __restrict__ values,
    const int* __restrict__ meas, const float* __restrict__ mask,
    const float* __restrict__ pw1, const float* __restrict__ pb1,
    const float* __restrict__ pw2, const float* __restrict__ pb2,
    const float* __restrict__ arw, const float* __restrict__ arb,
    const float* __restrict__ wk, const float* __restrict__ wq,
    const float* __restrict__ fw1, const float* __restrict__ fb1,
    const float* __restrict__ fw2, const float* __restrict__ fb2,
    const float* __restrict__ rw1, const float* __restrict__ rb1,
    const float* __restrict__ rw2, const float* __restrict__ rb2,
    float* __restrict__ out)
{
    extern __shared__ char SM[];
    float4* a_p1 = (float4*)(SM + OFF_WP1);
    float4* a_p2 = (float4*)(SM + OFF_WP2);
    float4* a_f1 = (float4*)(SM + OFF_WF1);
    float4* a_f2 = (float4*)(SM + OFF_WF2);
    float*  s_bias = (float*)(SM + OFF_BIAS);       // pb1,pb2,fb1,fb2,arb
    float*  s_comb = (float*)(SM + OFF_COMB);
    float*  s_epsi = (float*)(SM + OFF_EPSI);
    float*  s_enc  = (float*)(SM + OFF_ENC);
    float*  s_u    = (float*)(SM + OFF_U);
    float*  s_mk   = (float*)(SM + OFF_MASK);

    int tid  = threadIdx.x;
    int lane = tid & 31;
    int w    = tid >> 5;
    int b    = blockIdx.x >> 6;
    int chunk = blockIdx.x & 63;
    int pos0 = blockIdx.x * 32 + w * 4;             // global position base (warp)
    int lp0  = chunk * 32 + w * 4;                  // local position base (warp)

    // ======================= PHASE A =======================
    {
        // stage A weights (256 entries each, 1 iter per thread)
        int i4 = tid >> 5, l = tid & 31, r0 = i4 * 4;
        float p3 = (r0 + 3 < 31) ? pw1[(r0 + 3) * 32 + l] : 0.0f;
        float f3 = (r0 + 3 < 31) ? fw1[(r0 + 3) * 32 + l] : 0.0f;
        a_p1[tid] = make_float4(pw1[r0 * 32 + l], pw1[(r0 + 1) * 32 + l],
                                pw1[(r0 + 2) * 32 + l], p3);
        a_f1[tid] = make_float4(fw1[r0 * 32 + l], fw1[(r0 + 1) * 32 + l],
                                fw1[(r0 + 2) * 32 + l], f3);
        a_p2[tid] = make_float4(pw2[r0 * 32 + l], pw2[(r0 + 1) * 32 + l],
                                pw2[(r0 + 2) * 32 + l], pw2[(r0 + 3) * 32 + l]);
        a_f2[tid] = make_float4(fw2[r0 * 32 + l], fw2[(r0 + 1) * 32 + l],
                                fw2[(r0 + 2) * 32 + l], fw2[(r0 + 3) * 32 + l]);
        if (tid < 32)       s_bias[tid]       = pb1[tid];
        else if (tid < 64)  s_bias[tid]       = pb2[tid - 32];
        else if (tid < 96)  s_bias[tid]       = fb1[tid - 64];
        else if (tid < 128) s_bias[tid]       = fb2[tid - 96];
    }
    __syncthreads();

    float* sx = (float*)(SM + OFF_SX4);             // masked combined [(pos_l)*32+i]
    float* sh = (float*)(SM + OFF_SH4);
    float4* sx4 = (float4*)sx;
    float4* sh4 = (float4*)sh;

    float mk[4];
    #pragma unroll
    for (int q = 0; q < 4; q++) {
        int pos = pos0 + q;
        float t = times[pos], v = values[pos];
        mk[q] = mask[pos];
        int m = meas[pos];
        float xr = combined_lane(t, v, m, lane);
        s_comb[(w * 4 + q) * 32 + lane] = xr;       // raw (for phase B)
        sx[(w * 4 + q) * 32 + lane] = xr * mk[q];   // masked (for matvec)
    }
    if (lane == 0) {
        #pragma unroll
        for (int q = 0; q < 4; q++) s_mk[w * 4 + q] = mk[q];
    }
    __syncwarp();

    float acc[4];
    // psi layer 1
    #pragma unroll
    for (int q = 0; q < 4; q++) acc[q] = s_bias[lane];
    #pragma unroll
    for (int i4 = 0; i4 < 8; i4++) {
        float4 wv = a_p1[i4 * 32 + lane];
        #pragma unroll
        for (int q = 0; q < 4; q++) {
            float4 xv = sx4[(w * 4 + q) * 8 + i4];
            acc[q] += xv.x * wv.x; acc[q] += xv.y * wv.y;
            acc[q] += xv.z * wv.z; acc[q] += xv.w * wv.w;
        }
    }
    #pragma unroll
    for (int q = 0; q < 4; q++)
        sh[(w * 4 + q) * 32 + lane] = fmaxf(acc[q], 0.0f) * mk[q];
    __syncwarp();

    // psi layer 2 (+ chunk partial)
    #pragma unroll
    for (int q = 0; q < 4; q++) acc[q] = s_bias[32 + lane];
    #pragma unroll
    for (int i4 = 0; i4 < 8; i4++) {
        float4 wv = a_p2[i4 * 32 + lane];
        #pragma unroll
        for (int q = 0; q < 4; q++) {
            float4 xv = sh4[(w * 4 + q) * 8 + i4];
            acc[q] += xv.x * wv.x; acc[q] += xv.y * wv.y;
            acc[q] += xv.z * wv.z; acc[q] += xv.w * wv.w;
        }
    }
    {
        float psum = 0.0f;
        #pragma unroll
        for (int q = 0; q < 4; q++) {
            float ev = fmaxf(acc[q], 0.0f) * mk[q];
            s_epsi[(w * 4 + q) * 32 + lane] = ev;
            psum += ev;
        }
        ((float*)(SM + OFF_CH))[w * 32 + lane] = psum;   // s_part
    }
    __syncwarp();

    // phi layer 1
    #pragma unroll
    for (int q = 0; q < 4; q++) acc[q] = s_bias[64 + lane];
    #pragma unroll
    for (int i4 = 0; i4 < 8; i4++) {
        float4 wv = a_f1[i4 * 32 + lane];
        #pragma unroll
        for (int q = 0; q < 4; q++) {
            float4 xv = sx4[(w * 4 + q) * 8 + i4];
            acc[q] += xv.x * wv.x; acc[q] += xv.y * wv.y;
            acc[q] += xv.z * wv.z; acc[q] += xv.w * wv.w;
        }
    }
    #pragma unroll
    for (int q = 0; q < 4; q++)
        sh[(w * 4 + q) * 32 + lane] = fmaxf(acc[q], 0.0f) * mk[q];
    __syncwarp();

    // phi layer 2
    #pragma unroll
    for (int q = 0; q < 4; q++) acc[q] = s_bias[96 + lane];
    #pragma unroll
    for (int i4 = 0; i4 < 8; i4++) {
        float4 wv = a_f2[i4 * 32 + lane];
        #pragma unroll
        for (int q = 0; q < 4; q++) {
            float4 xv = sh4[(w * 4 + q) * 8 + i4];
            acc[q] += xv.x * wv.x; acc[q] += xv.y * wv.y;
            acc[q] += xv.z * wv.z; acc[q] += xv.w * wv.w;
        }
    }
    #pragma unroll
    for (int q = 0; q < 4; q++)
        s_enc[(w * 4 + q) * 32 + lane] = fmaxf(acc[q], 0.0f) * mk[q];

    __syncthreads();
    if (w == 0) {   // ct2 chunk total (reads s_part @ OFF_CH — untouched by staging)
        float* s_part = (float*)(SM + OFF_CH);
        float t = 0.0f;
        #pragma unroll
        for (int w2 = 0; w2 < 8; w2++) t += s_part[w2 * 32 + lane];
        g_ct2[(b * NCHUNK + chunk) * 32 + lane] = t;
    }

    // ---- stage phase B + C weights (A weights dead; overlaps barrier wait) ----
    float4* c_w1 = (float4*)(SM + OFF_CW1);
    float4* c_w2 = (float4*)(SM + OFF_CW2);
    float4* s_ar4 = (float4*)(SM + OFF_AR4);
    float*  s_we  = (float*)(SM + OFF_WE);
    #pragma unroll
    for (int i = tid; i < 2048; i += 256) {
        int kp = i >> 5, l = i & 31, k = kp * 2;
        c_w1[i] = make_float4(rw1[k * 64 + l],       rw1[k * 64 + l + 32],
                              rw1[(k + 1) * 64 + l], rw1[(k + 1) * 64 + l + 32]);
    }
    #pragma unroll
    for (int i = tid; i < 1024; i += 256) {
        int kp = i >> 5, l = i & 31, k = kp * 2;
        c_w2[i] = make_float4(rw2[k * 64 + l],       rw2[k * 64 + l + 32],
                              rw2[(k + 1) * 64 + l], rw2[(k + 1) * 64 + l + 32]);
    }
    {
        int i4 = tid >> 5, l = tid & 31, r0 = i4 * 4;
        s_ar4[tid] = make_float4(arw[r0 * 32 + l], arw[(r0 + 1) * 32 + l],
                                 arw[(r0 + 2) * 32 + l], arw[(r0 + 3) * 32 + l]);
    }
    if (tid < 252) {
        int j = tid >> 2, h = tid & 3;
        float s = 0.0f;
        #pragma unroll
        for (int d = 0; d < 16; d++)
            s += wk[j * 64 + d * 4 + h] * wq[h * 16 + d];
        s_we[tid] = s * 0.25f;
    } else {
        s_we[tid] = 0.0f;
    }
    if (tid < 32) s_bias[128 + tid] = arb[tid];

    grid_barrier(0);

    // ======================= PHASE B =======================
    {
        float* s_wp = (float*)(SM + OFF_WPX);
        float* s_g  = (float*)(SM + OFF_G4);
        float4* s_g4 = (float4*)s_g;
        float4* we4 = (float4*)s_we;

        float cq[4], xraw[4], mkq[4];
        {
            float eq[4];
            #pragma unroll
            for (int q = 0; q < 4; q++) {
                mkq[q]  = s_mk[w * 4 + q];
                xraw[q] = s_comb[(w * 4 + q) * 32 + lane];
                eq[q]   = s_epsi[(w * 4 + q) * 32 + lane];
            }
            cq[0] = eq[0];
            cq[1] = cq[0] + eq[1];
            cq[2] = cq[1] + eq[2];
            cq[3] = cq[2] + eq[3];
            s_wp[w * 32 + lane] = cq[3];
        }
        __syncthreads();

        float off;
        {
            const float* ct = g_ct2 + (b * NCHUNK) * 32 + lane;
            float o0 = 0.f, o1 = 0.f, o2 = 0.f, o3 = 0.f;
            int k = 0;
            for (; k + 4 <= chunk; k += 4) {
                o0 += ct[k * 32];       o1 += ct[(k + 1) * 32];
                o2 += ct[(k + 2) * 32]; o3 += ct[(k + 3) * 32];
            }
            for (; k < chunk; k++) o0 += ct[k * 32];
            off = (o0 + o1) + (o2 + o3);
        }
        #pragma unroll
        for (int w2 = 0; w2 < 8; w2++)
            if (w2 < w) off += s_wp[w2 * 32 + lane];

        #pragma unroll
        for (int q = 0; q < 4; q++) {
            float cum = off + cq[q];
            float agr = __fdividef(cum, (float)(lp0 + q + 1)) * mkq[q];
            s_g[(w * 4 + q) * 32 + lane] = agr;
        }
        __syncwarp();

        // agg matvec (32x32)
        float agg[4];
        #pragma unroll
        for (int q = 0; q < 4; q++) agg[q] = s_bias[128 + lane];
        #pragma unroll
        for (int i4 = 0; i4 < 8; i4++) {
            float4 wv = s_ar4[i4 * 32 + lane];
            #pragma unroll
            for (int q = 0; q < 4; q++) {
                float4 xv = s_g4[(w * 4 + q) * 8 + i4];
                agg[q] += xv.x * wv.x; agg[q] += xv.y * wv.y;
                agg[q] += xv.z * wv.z; agg[q] += xv.w * wv.w;
            }
        }

        // collapsed preattn
        float4 wec = we4[lane];
        float4 wea = we4[31 + lane];
        int hh = lane & 3;
        float ufull[4];
        #pragma unroll
        for (int q = 0; q < 4; q++) {
            float am = agg[q] * mkq[q];
            float p0 = xraw[q] * wec.x + am * wea.x;
            float p1 = xraw[q] * wec.y + am * wea.y;
            float p2 = xraw[q] * wec.z + am * wea.z;
            float p3 = xraw[q] * wec.w + am * wea.w;
            #pragma unroll
            for (int o = 16; o >= 1; o >>= 1) {
                p0 += __shfl_xor_sync(FULL, p0, o);
                p1 += __shfl_xor_sync(FULL, p1, o);
                p2 += __shfl_xor_sync(FULL, p2, o);
                p3 += __shfl_xor_sync(FULL, p3, o);
            }
            float ph = (hh == 0) ? p0 : (hh == 1) ? p1 : (hh == 2) ? p2 : p3;
            float pre = ph * mkq[q] * mkq[q];
            ufull[q] = expf(pre);
            if (lane < 4) s_u[(w * 4 + q) * 4 + lane] = ufull[q];
        }

        // ct4 chunk totals
        float* s_pn = (float*)(SM + OFF_PN);
        float* s_pd = (float*)(SM + OFF_PD);
        {
            float e2q[4];
            #pragma unroll
            for (int q = 0; q < 4; q++) e2q[q] = s_enc[(w * 4 + q) * 32 + lane];
            #pragma unroll
            for (int h = 0; h < 4; h++) {
                float s = 0.0f;
                #pragma unroll
                for (int q = 0; q < 4; q++)
                    s += __shfl_sync(FULL, ufull[q], h) * e2q[q];
                s_pn[(w * 4 + h) * 32 + lane] = s;
            }
            if (lane < 4)
                s_pd[w * 4 + lane] = ufull[0] + ufull[1] + ufull[2] + ufull[3];
        }
        __syncthreads();

        if (w < 4) {
            int h = w;
            float t = 0.0f;
            #pragma unroll
            for (int w2 = 0; w2 < 8; w2++) t += s_pn[(w2 * 4 + h) * 32 + lane];
            g_ct4n[((b * 4 + h) * NCHUNK + chunk) * 32 + lane] = t;
            if (lane == 0) {
                float td = 0.0f;
                #pragma unroll
                for (int w2 = 0; w2 < 8; w2++) td += s_pd[w2 * 4 + h];
                g_ct4d[(b * 4 + h) * NCHUNK + chunk] = td;
            }
        }
    }

    grid_barrier(1);

    // ======================= PHASE C =======================
    float* s_a = (float*)(SM + OFF_CA);
    float* s_h2 = (float*)(SM + OFF_CH);
    float4* c_w1r = (float4*)(SM + OFF_CW1);
    float4* c_w2r = (float4*)(SM + OFF_CW2);

    if (w < 4) {
        int h = w, bh = b * 4 + h;
        float accn;
        {
            const float* ct = g_ct4n + (bh * NCHUNK) * 32 + lane;
            float o0 = 0.f, o1 = 0.f, o2 = 0.f, o3 = 0.f;
            int k = 0;
            for (; k + 4 <= chunk; k += 4) {
                o0 += ct[k * 32];       o1 += ct[(k + 1) * 32];
                o2 += ct[(k + 2) * 32]; o3 += ct[(k + 3) * 32];
            }
            for (; k < chunk; k++) o0 += ct[k * 32];
            accn = (o0 + o1) + (o2 + o3);
        }
        float accu;
        {
            const float* cd = g_ct4d + bh * NCHUNK;
            float myd = 0.0f;
            if (lane < chunk)      myd  = cd[lane];
            if (lane + 32 < chunk) myd += cd[lane + 32];
            #pragma unroll
            for (int o = 16; o >= 1; o >>= 1) myd += __shfl_xor_sync(FULL, myd, o);
            accu = myd;
        }

        #pragma unroll
        for (int tile = 0; tile < 4; tile++) {
            int base = tile * 8;
            float uu[8], ee[8], mm[8];
            #pragma unroll
            for (int j = 0; j < 8; j++) {
                uu[j] = s_u[(base + j) * 4 + h];
                ee[j] = s_enc[(base + j) * 32 + lane];
                mm[j] = s_mk[base + j];
            }
            #pragma unroll
            for (int j = 0; j < 8; j++) {
                accn += uu[j] * ee[j];
                accu += uu[j];
                float sc = __fdividef(mm[j] * mm[j], accu);
                s_a[(base + j) * 128 + h * 32 + lane] = accn * sc;
            }
        }
    }
    __syncthreads();

    // rho MLP, Q=4 (R12-proven shape)
    {
        const float4* s_a4 = (const float4*)s_a;
        float mks[4];
        #pragma unroll
        for (int q = 0; q < 4; q++) mks[q] = s_mk[w * 4 + q];

        float acc0[4], acc1[4];
        {
            float b0 = rb1[lane], b1v = rb1[lane + 32];
            #pragma unroll
            for (int q = 0; q < 4; q++) { acc0[q] = b0; acc1[q] = b1v; }
        }

        #pragma unroll 4
        for (int g = 0; g < 32; g++) {
            float4 wa = c_w1r[(2 * g) * 32 + lane];
            float4 wb = c_w1r[(2 * g + 1) * 32 + lane];
            #pragma unroll
            for (int q = 0; q < 4; q++) {
                float4 av = s_a4[(w * 4 + q) * 32 + g];
                acc0[q] += av.x * wa.x; acc1[q] += av.x * wa.y;
                acc0[q] += av.y * wa.z; acc1[q] += av.y * wa.w;
                acc0[q] += av.z * wb.x; acc1[q] += av.z * wb.y;
                acc0[q] += av.w * wb.z; acc1[q] += av.w * wb.w;
            }
        }
        #pragma unroll
        for (int q = 0; q < 4; q++) {
            float* hp = s_h2 + (w * 4 + q) * 64;
            hp[lane]      = fmaxf(acc0[q], 0.0f) * mks[q];
            hp[lane + 32] = fmaxf(acc1[q], 0.0f) * mks[q];
        }
        __syncwarp();

        {
            float b0 = rb2[lane], b1v = rb2[lane + 32];
            #pragma unroll
            for (int q = 0; q < 4; q++) { acc0[q] = b0; acc1[q] = b1v; }
        }
        #pragma unroll 4
        for (int g = 0; g < 16; g++) {
            float4 wa = c_w2r[(2 * g) * 32 + lane];
            float4 wb = c_w2r[(2 * g + 1) * 32 + lane];
            #pragma unroll
            for (int q = 0; q < 4; q++) {
                float4 av = *(const float4*)(s_h2 + (w * 4 + q) * 64 + 4 * g);
                acc0[q] += av.x * wa.x; acc1[q] += av.x * wa.y;
                acc0[q] += av.y * wa.z; acc1[q] += av.y * wa.w;
                acc0[q] += av.z * wb.x; acc1[q] += av.z * wb.y;
                acc0[q] += av.w * wb.z; acc1[q] += av.w * wb.w;
            }
        }
        #pragma unroll
        for (int q = 0; q < 4; q++) {
            int gpos = pos0 + q;
            out[gpos * 64 + lane]      = fmaxf(acc0[q], 0.0f) * mks[q];
            out[gpos * 64 + lane + 32] = fmaxf(acc1[q], 0.0f) * mks[q];
        }
    }
}

// ---------------------------------------------------------------------------
extern "C" void kernel_launch(void* const* d_in, const int* in_sizes, int n_in,
                              void* d_out, int out_size)
{
    const float* times   = (const float*)d_in[0];
    const float* values  = (const float*)d_in[1];
    const int*   meas    = (const int*)  d_in[2];
    const float* mask    = (const float*)d_in[3];
    const float* psi_w1  = (const float*)d_in[4];
    const float* psi_b1  = (const float*)d_in[5];
    const float* psi_w2  = (const float*)d_in[6];
    const float* psi_b2  = (const float*)d_in[7];
    const float* arho_w  = (const float*)d_in[8];
    const float* arho_b  = (const float*)d_in[9];
    const float* W_k     = (const float*)d_in[10];
    const float* W_q     = (const float*)d_in[11];
    const float* phi_w1  = (const float*)d_in[12];
    const float* phi_b1  = (const float*)d_in[13];
    const float* phi_w2  = (const float*)d_in[14];
    const float* phi_b2  = (const float*)d_in[15];
    const float* rho_w1  = (const float*)d_in[16];
    const float* rho_b1  = (const float*)d_in[17];
    const float* rho_w2  = (const float*)d_in[18];
    const float* rho_b2  = (const float*)d_in[19];
    float* out = (float*)d_out;

    cudaFuncSetAttribute(mega, cudaFuncAttributeMaxDynamicSharedMemorySize,
                         SMEM_TOTAL);

    mega<<<GRID, 256, SMEM_TOTAL>>>(times, values, meas, mask,
                                    psi_w1, psi_b1, psi_w2, psi_b2,
                                    arho_w, arho_b, W_k, W_q,
                                    phi_w1, phi_b1, phi_w2, phi_b2,
                                    rho_w1, rho_b1, rho_w2, rho_b2, out);
}